// round 2
// baseline (speedup 1.0000x reference)
#include <cuda_runtime.h>
#include <math.h>

#define NN 50000
#define EE 625000
#define DD 128
#define ROWS_PER_BLOCK 64
#define GEMM_THREADS 256

// Scratch (device globals — no allocation allowed in kernel_launch)
__device__ int   g_deg[2 * NN];                 // [0:NN) fwd in-deg(+self), [NN:2NN) bwd
__device__ float g_hs_f[(size_t)NN * DD];       // (x@W_fwd) * dinv_f  (row-scaled)
__device__ float g_hs_b[(size_t)NN * DD];
__device__ float g_acc_f[(size_t)NN * DD];      // accumulators, init = hs (self loop)
__device__ float g_acc_b[(size_t)NN * DD];

__global__ void k_init_deg() {
    int i = blockIdx.x * blockDim.x + threadIdx.x;
    if (i < 2 * NN) g_deg[i] = 1;               // self-loop contributes 1
}

__global__ void k_count(const int* __restrict__ ei) {
    int e = blockIdx.x * blockDim.x + threadIdx.x;
    if (e < EE) {
        int s = ei[e];
        int d = ei[EE + e];
        atomicAdd(&g_deg[d], 1);                // fwd conv: degree by dst
        atomicAdd(&g_deg[NN + s], 1);           // bwd conv (edges reversed): by src
    }
}

// Fused dual GEMM + dinv row scale. Each block: 64 rows, 256 threads.
// Warp handles 8 rows x 128 cols; lane owns 4 consecutive cols (float4).
__global__ void __launch_bounds__(GEMM_THREADS)
k_gemm(const float* __restrict__ x,
       const float* __restrict__ Wf,
       const float* __restrict__ Wb) {
    extern __shared__ float sm[];
    float* sW = sm;                 // 128*128 floats (64 KB)
    float* sX = sm + DD * DD;       // 64*128 floats (32 KB)
    const int row0 = blockIdx.x * ROWS_PER_BLOCK;
    const int tid  = threadIdx.x;
    const int warp = tid >> 5, lane = tid & 31;

    // Load x tile (vectorized, zero-pad tail rows)
    for (int i = tid; i < ROWS_PER_BLOCK * DD / 4; i += GEMM_THREADS) {
        int r  = i >> 5;
        int gr = row0 + r;
        float4 v = make_float4(0.f, 0.f, 0.f, 0.f);
        if (gr < NN) v = reinterpret_cast<const float4*>(x)[(size_t)gr * 32 + (i & 31)];
        reinterpret_cast<float4*>(sX)[i] = v;
    }

    #pragma unroll
    for (int pass = 0; pass < 2; pass++) {
        const float* W = pass ? Wb : Wf;
        __syncthreads();            // (pass0: x tile done; pass1: sW readers done)
        for (int i = tid; i < DD * DD / 4; i += GEMM_THREADS)
            reinterpret_cast<float4*>(sW)[i] = reinterpret_cast<const float4*>(W)[i];
        __syncthreads();

        float4 acc[8];
        #pragma unroll
        for (int r = 0; r < 8; r++) acc[r] = make_float4(0.f, 0.f, 0.f, 0.f);

        const float* xbase = sX + (warp * 8) * DD;
        #pragma unroll 4
        for (int k4 = 0; k4 < 32; k4++) {
            float4 xv[8];
            #pragma unroll
            for (int r = 0; r < 8; r++)
                xv[r] = reinterpret_cast<const float4*>(xbase + (size_t)r * DD)[k4];
            #pragma unroll
            for (int kk = 0; kk < 4; kk++) {
                float4 w = reinterpret_cast<const float4*>(sW)[(k4 * 4 + kk) * 32 + lane];
                #pragma unroll
                for (int r = 0; r < 8; r++) {
                    float xs = (kk == 0) ? xv[r].x : (kk == 1) ? xv[r].y
                             : (kk == 2) ? xv[r].z : xv[r].w;
                    acc[r].x += xs * w.x;
                    acc[r].y += xs * w.y;
                    acc[r].z += xs * w.z;
                    acc[r].w += xs * w.w;
                }
            }
        }

        float* hs = pass ? g_hs_b  : g_hs_f;
        float* ac = pass ? g_acc_b : g_acc_f;
        const int degoff = pass ? NN : 0;
        #pragma unroll
        for (int r = 0; r < 8; r++) {
            int gr = row0 + warp * 8 + r;
            if (gr < NN) {
                float dinv = rsqrtf((float)g_deg[degoff + gr]);
                float4 o = acc[r];
                o.x *= dinv; o.y *= dinv; o.z *= dinv; o.w *= dinv;
                reinterpret_cast<float4*>(hs)[(size_t)gr * 32 + lane] = o;
                reinterpret_cast<float4*>(ac)[(size_t)gr * 32 + lane] = o;
            }
        }
    }
}

// One warp per (conv, edge): gather hs[src] row (512B), vector atomic-add into acc[dst].
__global__ void k_scatter(const int* __restrict__ ei) {
    unsigned gw = (blockIdx.x * blockDim.x + threadIdx.x) >> 5;
    int lane = threadIdx.x & 31;
    if (gw >= 2u * EE) return;
    int c = (gw >= (unsigned)EE);
    int e = c ? (int)(gw - EE) : (int)gw;
    int s, d;
    if (!c) { s = ei[e];      d = ei[EE + e]; }
    else    { s = ei[EE + e]; d = ei[e];      }
    const float4* hs = reinterpret_cast<const float4*>(c ? g_hs_b : g_hs_f);
    float*       acc = c ? g_acc_b : g_acc_f;
    float4 v = hs[(size_t)s * 32 + lane];
    float* p = acc + (size_t)d * DD + lane * 4;
    asm volatile("red.global.add.v4.f32 [%0], {%1, %2, %3, %4};"
                 :: "l"(p), "f"(v.x), "f"(v.y), "f"(v.z), "f"(v.w)
                 : "memory");
}

// out = relu(dinv_f*acc_f + dinv_b*acc_b + b_f + b_b)
__global__ void k_finalize(const float* __restrict__ bf,
                           const float* __restrict__ bb,
                           float* __restrict__ out) {
    int i = blockIdx.x * blockDim.x + threadIdx.x;      // over NN*32 float4s
    if (i >= NN * 32) return;
    int v  = i >> 5;
    int c4 = i & 31;
    float df = rsqrtf((float)g_deg[v]);
    float db = rsqrtf((float)g_deg[NN + v]);
    float4 af = reinterpret_cast<const float4*>(g_acc_f)[i];
    float4 ab = reinterpret_cast<const float4*>(g_acc_b)[i];
    float4 vf = reinterpret_cast<const float4*>(bf)[c4];
    float4 vb = reinterpret_cast<const float4*>(bb)[c4];
    float4 o;
    o.x = fmaxf(af.x * df + ab.x * db + vf.x + vb.x, 0.f);
    o.y = fmaxf(af.y * df + ab.y * db + vf.y + vb.y, 0.f);
    o.z = fmaxf(af.z * df + ab.z * db + vf.z + vb.z, 0.f);
    o.w = fmaxf(af.w * df + ab.w * db + vf.w + vb.w, 0.f);
    reinterpret_cast<float4*>(out)[i] = o;
}

extern "C" void kernel_launch(void* const* d_in, const int* in_sizes, int n_in,
                              void* d_out, int out_size) {
    const float* x  = (const float*)d_in[0];
    const int*   ei = (const int*)  d_in[1];
    const float* Wf = (const float*)d_in[2];
    const float* bf = (const float*)d_in[3];
    const float* Wb = (const float*)d_in[4];
    const float* bb = (const float*)d_in[5];
    float*       out = (float*)d_out;

    const int smem = (DD * DD + ROWS_PER_BLOCK * DD) * (int)sizeof(float); // 96 KB
    cudaFuncSetAttribute(k_gemm, cudaFuncAttributeMaxDynamicSharedMemorySize, smem);

    k_init_deg<<<(2 * NN + 255) / 256, 256>>>();
    k_count<<<(EE + 255) / 256, 256>>>(ei);
    k_gemm<<<(NN + ROWS_PER_BLOCK - 1) / ROWS_PER_BLOCK, GEMM_THREADS, smem>>>(x, Wf, Wb);
    k_scatter<<<(2u * EE * 32u) / 256u, 256>>>(ei);      // exactly 156250 blocks
    k_finalize<<<(NN * 32 + 255) / 256, 256>>>(bf, bb, out);
}